// round 5
// baseline (speedup 1.0000x reference)
#include <cuda_runtime.h>
#include <math.h>

#define BB 256
#define SS 256
#define HH 512
#define INF 512
#define XROW 514   // IN + 2
#define NBLK 128   // persistent recurrence blocks (1/SM, co-resident)
#define KC 64      // k-chunk for staged h

// SMEM partition for rec kernel (dynamic): ws2 64KB | As 2x64KB | Gs 32KB
#define SM_WS2   0
#define SM_AS    65536
#define SM_GS    (65536 + 131072)
#define SM_TOTAL (65536 + 131072 + 32768)   // 229376

// Scratch (device globals; no runtime allocation allowed)
__device__ __align__(128) float g_G[(size_t)SS * 8 * BB * HH]; // [s][gate][b][h]
__device__ __align__(128) float g_hT[2][HH * BB];              // [h][b], ping-pong
__device__ unsigned g_count;                                   // barrier ctr, self-resetting

__device__ __forceinline__ float sigf(float x) { return 1.0f / (1.0f + expf(-x)); }

// ---- f32x2 packed-FMA helpers ----
__device__ __forceinline__ unsigned long long pk2(float x, float y) {
    unsigned long long r;
    asm("mov.b64 %0, {%1, %2};" : "=l"(r) : "f"(x), "f"(y));
    return r;
}
__device__ __forceinline__ void fma2(unsigned long long& d, unsigned long long a,
                                     unsigned long long b) {
    asm("fma.rn.f32x2 %0, %1, %2, %0;" : "+l"(d) : "l"(a), "l"(b));
}
__device__ __forceinline__ float2 upk2(unsigned long long v) {
    float2 f;
    asm("mov.b64 {%0, %1}, %2;" : "=f"(f.x), "=f"(f.y) : "l"(v));
    return f;
}

// ---- cp.async helpers (cg = L2-only, bypasses stale L1) ----
__device__ __forceinline__ void cpa16(void* dst_smem, const void* src) {
    unsigned d = (unsigned)__cvta_generic_to_shared(dst_smem);
    asm volatile("cp.async.cg.shared.global [%0], [%1], 16;" :: "r"(d), "l"(src));
}
#define CP_COMMIT() asm volatile("cp.async.commit_group;" ::: "memory")
#define CP_WAIT(n)  asm volatile("cp.async.wait_group %0;" :: "n"(n) : "memory")

__device__ __forceinline__ unsigned ld_cg_u32(const unsigned* p) {
    unsigned v;
    asm volatile("ld.global.cg.u32 %0, [%1];" : "=r"(v) : "l"(p));
    return v;
}

struct ProjArgs {
    const float* x;
    const float* Wx[8];
    const float* bias[8];
    const float* aux1[8];
    const float* aux2[8];
};

// ---------------------------------------------------------------------------
// Projection GEMM: G[s][g][b][h] = x @ Wx_g + extras.
// grid = (8, 1024, 8 gates), block = 256. 64x64 tile, 4m x 4n per thread.
// A pre-duplicated as (a,a) f32x2 pairs; B read as natural float4 pairs.
// Inner loop: 3 LDS.128 + 8 FFMA2 per kk (16 MACs).
// ---------------------------------------------------------------------------
__global__ void proj_kernel(ProjArgs p) {
    const int g  = blockIdx.z;
    const int m0 = blockIdx.y * 64;
    const int n0 = blockIdx.x * 64;

    __shared__ __align__(16) unsigned long long As2[16][66];  // (a,a) [kk][m]
    __shared__ __align__(16) float Bs[16][68];                // [kk][n]

    const int tid = threadIdx.x;
    const int tm = tid >> 4;   // 0..15 -> m rows tm*4 .. +3
    const int tn = tid & 15;   // 0..15 -> n cols tn*4 .. +3

    const float* W = p.Wx[g];

    unsigned long long acc2[4][2];
    #pragma unroll
    for (int i = 0; i < 4; i++) { acc2[i][0] = 0ULL; acc2[i][1] = 0ULL; }

    for (int k0 = 0; k0 < INF; k0 += 16) {
        // Stage A transposed + duplicated: thread covers m = tid&63, kk = (tid>>6)*4..+3
        {
            int m  = tid & 63;
            int kq = tid >> 6;
            const float* xr = &p.x[(size_t)(m0 + m) * XROW + 2 + k0 + kq * 4];
            float a0 = xr[0], a1 = xr[1], a2 = xr[2], a3 = xr[3];
            As2[kq * 4 + 0][m] = pk2(a0, a0);
            As2[kq * 4 + 1][m] = pk2(a1, a1);
            As2[kq * 4 + 2][m] = pk2(a2, a2);
            As2[kq * 4 + 3][m] = pk2(a3, a3);
        }
        // Stage B: float4 coalesced
        {
            int idx = tid * 4;
            int kk = idx >> 6;
            int hc = idx & 63;
            float4 w = *(const float4*)&W[(size_t)(k0 + kk) * HH + n0 + hc];
            *(float4*)&Bs[kk][hc] = w;
        }
        __syncthreads();

        #pragma unroll
        for (int kk = 0; kk < 16; kk++) {
            ulonglong2 a01 = *(const ulonglong2*)&As2[kk][tm * 4];
            ulonglong2 a23 = *(const ulonglong2*)&As2[kk][tm * 4 + 2];
            ulonglong2 bq  = *(const ulonglong2*)&Bs[kk][tn * 4];
            fma2(acc2[0][0], a01.x, bq.x); fma2(acc2[0][1], a01.x, bq.y);
            fma2(acc2[1][0], a01.y, bq.x); fma2(acc2[1][1], a01.y, bq.y);
            fma2(acc2[2][0], a23.x, bq.x); fma2(acc2[2][1], a23.x, bq.y);
            fma2(acc2[3][0], a23.y, bq.x); fma2(acc2[3][1], a23.y, bq.y);
        }
        __syncthreads();
    }

    const float* bias = p.bias[g];
    const float* a1p = p.aux1[g];
    const float* a2p = p.aux2[g];

    float4 bias4 = *(const float4*)&bias[n0 + tn * 4];
    float4 a14 = make_float4(0.f, 0.f, 0.f, 0.f);
    float4 a24 = make_float4(0.f, 0.f, 0.f, 0.f);
    if (g >= 3) a14 = *(const float4*)&a1p[n0 + tn * 4];
    if (g == 7) a24 = *(const float4*)&a2p[n0 + tn * 4];

    #pragma unroll
    for (int i = 0; i < 4; i++) {
        int m = m0 + tm * 4 + i;
        int bidx = m / SS;
        int sidx = m % SS;
        float Tt = p.x[(size_t)m * XROW + 0];
        float Dt = p.x[(size_t)m * XROW + 1];
        size_t base = (((size_t)sidx * 8 + g) * BB + bidx) * HH;
        float2 lo = upk2(acc2[i][0]);
        float2 hi = upk2(acc2[i][1]);
        float4 v = make_float4(lo.x + bias4.x, lo.y + bias4.y,
                               hi.x + bias4.z, hi.y + bias4.w);
        if (g == 3 || g == 4) {
            v.x += sigf(Tt * a14.x); v.y += sigf(Tt * a14.y);
            v.z += sigf(Tt * a14.z); v.w += sigf(Tt * a14.w);
        } else if (g == 5 || g == 6) {
            v.x += sigf(Dt * a14.x); v.y += sigf(Dt * a14.y);
            v.z += sigf(Dt * a14.z); v.w += sigf(Dt * a14.w);
        } else if (g == 7) {
            v.x += Tt * a14.x + Dt * a24.x; v.y += Tt * a14.y + Dt * a24.y;
            v.z += Tt * a14.z + Dt * a24.z; v.w += Tt * a14.w + Dt * a24.w;
        }
        *(float4*)&g_G[base + n0 + tn * 4] = v;
    }
}

// ---------------------------------------------------------------------------
// Persistent recurrence. 128 blocks x 256 thr. Block owns h-cols [h0,h0+4)
// x 4 gates; weights SMEM-resident as (w,w) pairs; h staged via cp.async.
// Grid barrier: bar.sync + SINGLE elected thread does fence/atomic (the
// R3 version had 256 threadfences/step — each is a CCTL.IVALL on sm_103a).
// ---------------------------------------------------------------------------
__global__ void __launch_bounds__(256, 1)
rec_kernel(const float* __restrict__ Whi, const float* __restrict__ Whf,
           const float* __restrict__ Whc, const float* __restrict__ Who,
           float* __restrict__ out, unsigned long long out_size) {
    extern __shared__ __align__(16) char smem_raw[];
    unsigned long long* ws2 = (unsigned long long*)(smem_raw + SM_WS2); // [k*16+h*4+g]
    float* Asmem = (float*)(smem_raw + SM_AS);                          // 2 x [KC][256]
    float* Gs    = (float*)(smem_raw + SM_GS);                          // [g][b][4h]

    const int tid = threadIdx.x;
    const int h0 = blockIdx.x * 4;
    const int hg = tid & 3;
    const int b0 = (tid >> 2) * 4;

    // Preload duplicated weight pairs: ws2[k][h][g] = (w,w)
    {
        const float* Wg[4] = {Whi, Whf, Whc, Who};
        for (int idx = tid; idx < HH * 16; idx += 256) {
            int k = idx >> 4, hc = (idx >> 2) & 3, g = idx & 3;
            float w = __ldg(&Wg[g][(size_t)k * HH + h0 + hc]);
            ws2[(size_t)k * 16 + hc * 4 + g] = pk2(w, w);
        }
    }
    __syncthreads();

    float cst[4] = {0.f, 0.f, 0.f, 0.f};

    for (int t = 0; t < SS; t++) {
        const float* hT = g_hT[t & 1];
        float* hTn = g_hT[(t + 1) & 1];

        if (t > 0) {   // chunk 0 of h (h == 0 at t == 0 -> skip GEMM entirely)
            const char* src = (const char*)hT;
            #pragma unroll
            for (int i = 0; i < 16; i++) {
                int off = (i * 256 + tid) * 16;
                cpa16((char*)Asmem + off, src + off);
            }
            CP_COMMIT();
        }
        // G slices [t][g][b=tid][h0..h0+3]
        {
            #pragma unroll
            for (int g = 0; g < 8; g++) {
                const float* srcg = g_G + (((size_t)t * 8 + g) * BB + tid) * HH + h0;
                cpa16(Gs + (g * 256 + tid) * 4, srcg);
            }
            CP_COMMIT();
        }

        unsigned long long acc[2][4];
        #pragma unroll
        for (int rp = 0; rp < 2; rp++)
            #pragma unroll
            for (int g = 0; g < 4; g++) acc[rp][g] = 0ULL;

        if (t > 0) {
            for (int c = 0; c < HH / KC; c++) {
                if (c < HH / KC - 1) {
                    const char* src = (const char*)hT + (size_t)(c + 1) * KC * 256 * 4;
                    char* dst = (char*)Asmem + ((c + 1) & 1) * (KC * 256 * 4);
                    #pragma unroll
                    for (int i = 0; i < 16; i++) {
                        int off = (i * 256 + tid) * 16;
                        cpa16(dst + off, src + off);
                    }
                    CP_COMMIT();
                }
                if (c == 0)                 CP_WAIT(2);
                else if (c < HH / KC - 1)   CP_WAIT(1);
                else                        CP_WAIT(0);
                __syncthreads();

                const float* A = Asmem + (c & 1) * (KC * 256) + b0;
                const unsigned long long* wp = ws2 + (size_t)c * KC * 16 + hg * 4;
                #pragma unroll 8
                for (int k = 0; k < KC; k++) {
                    ulonglong2 aq  = *(const ulonglong2*)(A + k * 256);
                    ulonglong2 w01 = *(const ulonglong2*)(wp + k * 16);
                    ulonglong2 w23 = *(const ulonglong2*)(wp + k * 16 + 2);
                    fma2(acc[0][0], aq.x, w01.x); fma2(acc[1][0], aq.y, w01.x);
                    fma2(acc[0][1], aq.x, w01.y); fma2(acc[1][1], aq.y, w01.y);
                    fma2(acc[0][2], aq.x, w23.x); fma2(acc[1][2], aq.y, w23.x);
                    fma2(acc[0][3], aq.x, w23.y); fma2(acc[1][3], aq.y, w23.y);
                }
                __syncthreads();
            }
        } else {
            CP_WAIT(0);
            __syncthreads();
        }

        float y[4][4];
        #pragma unroll
        for (int g = 0; g < 4; g++) {
            float2 lo = upk2(acc[0][g]);
            float2 hi = upk2(acc[1][g]);
            y[g][0] = lo.x; y[g][1] = lo.y; y[g][2] = hi.x; y[g][3] = hi.y;
        }

        float hn[4];
        #pragma unroll
        for (int r = 0; r < 4; r++) {
            int b = b0 + r;
            float xi = Gs[(0 * 256 + b) * 4 + hg] + y[0][r];
            float xf = Gs[(1 * 256 + b) * 4 + hg] + y[1][r];
            float xc = Gs[(2 * 256 + b) * 4 + hg] + y[2][r];
            float t1 = Gs[(3 * 256 + b) * 4 + hg];
            float t2 = Gs[(4 * 256 + b) * 4 + hg];
            float d1 = Gs[(5 * 256 + b) * 4 + hg];
            float d2 = Gs[(6 * 256 + b) * 4 + hg];
            float o  = Gs[(7 * 256 + b) * 4 + hg] + y[3][r];

            float it = sigf(xi);
            float ft = sigf(xf);
            float jj = tanhf(xc);
            float T1 = sigf(t1), T2 = sigf(t2), D1 = sigf(d1), D2 = sigf(d2);
            float fc = ft * cst[r];
            float ij = it * jj;
            float chat = fc + ij * T1 * D1;
            float cnew = fc + ij * T2 * D2;
            float ot = sigf(o);
            hn[r] = ot * tanhf(chat);
            cst[r] = cnew;
        }

        // next-step hidden state: [h][b], float4 over b
        *(float4*)&hTn[(h0 + hg) * BB + b0] = make_float4(hn[0], hn[1], hn[2], hn[3]);

        // stage hn (and c at last step) for coalesced STG
        float* hs = Asmem;
        float* cs = Asmem + 4096;
        #pragma unroll
        for (int r = 0; r < 4; r++) hs[(b0 + r) * 4 + hg] = hn[r];
        if (t == SS - 1) {
            #pragma unroll
            for (int r = 0; r < 4; r++) cs[(b0 + r) * 4 + hg] = cst[r];
        }
        __syncthreads();
        {
            float4 v = *(const float4*)&hs[tid * 4];
            *(float4*)&out[((size_t)tid * SS + t) * HH + h0] = v;
            if (t == SS - 1) {
                unsigned long long base = (unsigned long long)BB * SS * HH;
                unsigned long long o1 = base + (unsigned long long)tid * HH + h0;
                unsigned long long o2 = o1 + (unsigned long long)BB * HH;
                if (o1 + 4 <= out_size) *(float4*)&out[o1] = v;
                if (o2 + 4 <= out_size) *(float4*)&out[o2] = *(const float4*)&cs[tid * 4];
            }
        }

        if (t < SS - 1) {
            // grid barrier: cooperative-groups idiom — fence/atomic by ONE thread
            __syncthreads();
            if (tid == 0) {
                __threadfence();                       // release (single CCTL)
                atomicAdd(&g_count, 1u);
                unsigned target = (unsigned)(t + 1) * (unsigned)NBLK;
                while (ld_cg_u32(&g_count) < target) { __nanosleep(32); }
                __threadfence();                       // acquire
            }
            __syncthreads();
        }
    }

    // Self-resetting counter: last of the final 128 arrivals zeroes it so the
    // next graph replay starts from 0 (deterministic).
    if (tid == 0) {
        unsigned old = atomicAdd(&g_count, 1u);
        if (old == (unsigned)(SS * NBLK - 1)) atomicExch(&g_count, 0u);
    }
}

extern "C" void kernel_launch(void* const* d_in, const int* in_sizes, int n_in,
                              void* d_out, int out_size) {
    const float* x = (const float*)d_in[0];

    ProjArgs pa = {};
    pa.x = x;
    pa.Wx[0] = (const float*)d_in[1];  pa.bias[0] = (const float*)d_in[3];
    pa.Wx[1] = (const float*)d_in[4];  pa.bias[1] = (const float*)d_in[6];
    pa.Wx[2] = (const float*)d_in[7];  pa.bias[2] = (const float*)d_in[9];
    pa.Wx[3] = (const float*)d_in[10]; pa.aux1[3] = (const float*)d_in[11]; pa.bias[3] = (const float*)d_in[12];
    pa.Wx[4] = (const float*)d_in[13]; pa.aux1[4] = (const float*)d_in[14]; pa.bias[4] = (const float*)d_in[15];
    pa.Wx[5] = (const float*)d_in[16]; pa.aux1[5] = (const float*)d_in[17]; pa.bias[5] = (const float*)d_in[18];
    pa.Wx[6] = (const float*)d_in[19]; pa.aux1[6] = (const float*)d_in[20]; pa.bias[6] = (const float*)d_in[21];
    pa.Wx[7] = (const float*)d_in[22]; pa.aux1[7] = (const float*)d_in[24]; pa.aux2[7] = (const float*)d_in[25];
    pa.bias[7] = (const float*)d_in[26];

    const float* Whi = (const float*)d_in[2];
    const float* Whf = (const float*)d_in[5];
    const float* Whc = (const float*)d_in[8];
    const float* Who = (const float*)d_in[23];

    float* out = (float*)d_out;

    cudaFuncSetAttribute(rec_kernel, cudaFuncAttributeMaxDynamicSharedMemorySize,
                         SM_TOTAL);

    dim3 pgrid(HH / 64, (BB * SS) / 64, 8);
    proj_kernel<<<pgrid, 256>>>(pa);

    rec_kernel<<<NBLK, 256, SM_TOTAL>>>(Whi, Whf, Whc, Who, out,
                                        (unsigned long long)out_size);
}

// round 7
// speedup vs baseline: 1.0920x; 1.0920x over previous
#include <cuda_runtime.h>
#include <math.h>

#define BB 256
#define SS 256
#define HH 512
#define INF 512
#define XROW 514   // IN + 2
#define NBLK 128   // persistent recurrence blocks (1/SM, co-resident)
#define KC 32      // k-chunk for staged h
#define NCHUNK (HH / KC)          // 16
#define CBYTES (KC * 256 * 4)     // 32768 per chunk

// SMEM partition for rec kernel: ws2 64KB | As 4x32KB | Gs 32KB = 224KB
#define SM_WS2   0
#define SM_AS    65536
#define SM_GS    (65536 + 131072)
#define SM_TOTAL (65536 + 131072 + 32768)   // 229376

// Scratch (device globals; no runtime allocation allowed)
__device__ __align__(128) float g_G[(size_t)SS * 8 * BB * HH]; // [s][gate][b][h]
__device__ __align__(128) float g_hT[2][HH * BB];              // [h][b], ping-pong
__device__ unsigned g_count;                                   // barrier ctr, self-resetting

// ---- fast activations (HW MUFU paths; ~1e-6 err vs 1e-3 tolerance) ----
__device__ __forceinline__ float sigf(float x) {
    return __fdividef(1.0f, 1.0f + __expf(-x));
}
__device__ __forceinline__ float tanh_fast(float x) {
    float a = fabsf(x);
    float e = __expf(-2.0f * a);                 // in (0,1], no overflow
    float t = __fdividef(1.0f - e, 1.0f + e);
    return copysignf(t, x);
}

// ---- f32x2 packed-FMA helpers ----
__device__ __forceinline__ unsigned long long pk2(float x, float y) {
    unsigned long long r;
    asm("mov.b64 %0, {%1, %2};" : "=l"(r) : "f"(x), "f"(y));
    return r;
}
__device__ __forceinline__ void fma2(unsigned long long& d, unsigned long long a,
                                     unsigned long long b) {
    asm("fma.rn.f32x2 %0, %1, %2, %0;" : "+l"(d) : "l"(a), "l"(b));
}
__device__ __forceinline__ float2 upk2(unsigned long long v) {
    float2 f;
    asm("mov.b64 {%0, %1}, %2;" : "=f"(f.x), "=f"(f.y) : "l"(v));
    return f;
}

// ---- cp.async helpers (cg = L2-only, bypasses stale L1) ----
__device__ __forceinline__ void cpa16(void* dst_smem, const void* src) {
    unsigned d = (unsigned)__cvta_generic_to_shared(dst_smem);
    asm volatile("cp.async.cg.shared.global [%0], [%1], 16;" :: "r"(d), "l"(src));
}
#define CP_COMMIT() asm volatile("cp.async.commit_group;" ::: "memory")
#define CP_WAIT(n)  asm volatile("cp.async.wait_group %0;" :: "n"(n) : "memory")

__device__ __forceinline__ unsigned ld_cg_u32(const unsigned* p) {
    unsigned v;
    asm volatile("ld.global.cg.u32 %0, [%1];" : "=r"(v) : "l"(p));
    return v;
}

struct ProjArgs {
    const float* x;
    const float* Wx[8];
    const float* bias[8];
    const float* aux1[8];
    const float* aux2[8];
};

// ---------------------------------------------------------------------------
// Projection GEMM: G[s][g][b][h] = x @ Wx_g + extras.
// grid = (8, 1024, 8 gates), block = 256. 64x64 tile, 4m x 4n per thread.
// A staged COALESCED (64B-contiguous LDG) into dup (a,a) f32x2 pairs.
// Inner loop: 3 LDS.128 + 8 FFMA2 per kk (16 MACs) — FMA-issue-bound.
// ---------------------------------------------------------------------------
__global__ void proj_kernel(ProjArgs p) {
    const int g  = blockIdx.z;
    const int m0 = blockIdx.y * 64;
    const int n0 = blockIdx.x * 64;

    __shared__ __align__(16) unsigned long long As2[16][66];  // (a,a) [kk][m]
    __shared__ __align__(16) float Bs[16][68];                // [kk][n]

    const int tid = threadIdx.x;
    const int tm = tid >> 4;   // 0..15 -> m rows tm*4 .. +3
    const int tn = tid & 15;   // 0..15 -> n cols tn*4 .. +3

    const float* W = p.Wx[g];

    unsigned long long acc2[4][2];
    #pragma unroll
    for (int i = 0; i < 4; i++) { acc2[i][0] = 0ULL; acc2[i][1] = 0ULL; }

    const int kk_ld = tid & 15;    // A-staging lane mapping (coalesced in k)
    const int mr_ld = tid >> 4;

    for (int k0 = 0; k0 < INF; k0 += 16) {
        // Stage A: coalesced LDG (16 lanes x consecutive k), STS duplicated
        #pragma unroll
        for (int q = 0; q < 4; q++) {
            int m = q * 16 + mr_ld;
            float a = p.x[(size_t)(m0 + m) * XROW + 2 + k0 + kk_ld];
            As2[kk_ld][m] = pk2(a, a);
        }
        // Stage B: float4 coalesced, natural layout
        {
            int idx = tid * 4;
            int kb = idx >> 6;
            int hc = idx & 63;
            float4 w = *(const float4*)&W[(size_t)(k0 + kb) * HH + n0 + hc];
            *(float4*)&Bs[kb][hc] = w;
        }
        __syncthreads();

        #pragma unroll
        for (int kk = 0; kk < 16; kk++) {
            ulonglong2 a01 = *(const ulonglong2*)&As2[kk][tm * 4];
            ulonglong2 a23 = *(const ulonglong2*)&As2[kk][tm * 4 + 2];
            ulonglong2 bq  = *(const ulonglong2*)&Bs[kk][tn * 4];
            fma2(acc2[0][0], a01.x, bq.x); fma2(acc2[0][1], a01.x, bq.y);
            fma2(acc2[1][0], a01.y, bq.x); fma2(acc2[1][1], a01.y, bq.y);
            fma2(acc2[2][0], a23.x, bq.x); fma2(acc2[2][1], a23.x, bq.y);
            fma2(acc2[3][0], a23.y, bq.x); fma2(acc2[3][1], a23.y, bq.y);
        }
        __syncthreads();
    }

    const float* bias = p.bias[g];
    const float* a1p = p.aux1[g];
    const float* a2p = p.aux2[g];

    float4 bias4 = *(const float4*)&bias[n0 + tn * 4];
    float4 a14 = make_float4(0.f, 0.f, 0.f, 0.f);
    float4 a24 = make_float4(0.f, 0.f, 0.f, 0.f);
    if (g >= 3) a14 = *(const float4*)&a1p[n0 + tn * 4];
    if (g == 7) a24 = *(const float4*)&a2p[n0 + tn * 4];

    #pragma unroll
    for (int i = 0; i < 4; i++) {
        int m = m0 + tm * 4 + i;
        int bidx = m / SS;
        int sidx = m % SS;
        float Tt = p.x[(size_t)m * XROW + 0];
        float Dt = p.x[(size_t)m * XROW + 1];
        size_t base = (((size_t)sidx * 8 + g) * BB + bidx) * HH;
        float2 lo = upk2(acc2[i][0]);
        float2 hi = upk2(acc2[i][1]);
        float4 v = make_float4(lo.x + bias4.x, lo.y + bias4.y,
                               hi.x + bias4.z, hi.y + bias4.w);
        if (g == 3 || g == 4) {
            v.x += sigf(Tt * a14.x); v.y += sigf(Tt * a14.y);
            v.z += sigf(Tt * a14.z); v.w += sigf(Tt * a14.w);
        } else if (g == 5 || g == 6) {
            v.x += sigf(Dt * a14.x); v.y += sigf(Dt * a14.y);
            v.z += sigf(Dt * a14.z); v.w += sigf(Dt * a14.w);
        } else if (g == 7) {
            v.x += Tt * a14.x + Dt * a24.x; v.y += Tt * a14.y + Dt * a24.y;
            v.z += Tt * a14.z + Dt * a24.z; v.w += Tt * a14.w + Dt * a24.w;
        }
        *(float4*)&g_G[base + n0 + tn * 4] = v;
    }
}

// ---------------------------------------------------------------------------
// Persistent recurrence. 128 blocks x 256 thr. Block owns h-cols [h0,h0+4)
// x 4 gates; weights SMEM-resident as (w,w) pairs. h staged via cp.async in a
// 4-buffer / 3-chunk-deep pipeline (KC=32). Fast-MUFU epilogue. Grid barrier:
// bar.sync + single elected fence/atomic.
// ---------------------------------------------------------------------------
__global__ void __launch_bounds__(256, 1)
rec_kernel(const float* __restrict__ Whi, const float* __restrict__ Whf,
           const float* __restrict__ Whc, const float* __restrict__ Who,
           float* __restrict__ out, unsigned long long out_size) {
    extern __shared__ __align__(16) char smem_raw[];
    unsigned long long* ws2 = (unsigned long long*)(smem_raw + SM_WS2); // [k*16+h*4+g]
    float* Asmem = (float*)(smem_raw + SM_AS);                          // 4 x [KC][256]
    float* Gs    = (float*)(smem_raw + SM_GS);                          // [g][b][4h]

    const int tid = threadIdx.x;
    const int h0 = blockIdx.x * 4;
    const int hg = tid & 3;
    const int b0 = (tid >> 2) * 4;

    // Preload duplicated weight pairs: ws2[k][h][g] = (w,w)
    {
        const float* Wg[4] = {Whi, Whf, Whc, Who};
        for (int idx = tid; idx < HH * 16; idx += 256) {
            int k = idx >> 4, hc = (idx >> 2) & 3, g = idx & 3;
            float w = __ldg(&Wg[g][(size_t)k * HH + h0 + hc]);
            ws2[(size_t)k * 16 + hc * 4 + g] = pk2(w, w);
        }
    }
    __syncthreads();

    float cst[4] = {0.f, 0.f, 0.f, 0.f};

    for (int t = 0; t < SS; t++) {
        const float* hT = g_hT[t & 1];
        float* hTn = g_hT[(t + 1) & 1];

        // G prefetch first (oldest group; done long before epilogue)
        {
            #pragma unroll
            for (int g = 0; g < 8; g++) {
                const float* srcg = g_G + (((size_t)t * 8 + g) * BB + tid) * HH + h0;
                cpa16(Gs + (g * 256 + tid) * 4, srcg);
            }
            CP_COMMIT();
        }

        unsigned long long acc[2][4];
        #pragma unroll
        for (int rp = 0; rp < 2; rp++)
            #pragma unroll
            for (int g = 0; g < 4; g++) acc[rp][g] = 0ULL;

        if (t > 0) {      // h == 0 at t == 0 -> skip GEMM entirely
            // prime pipeline: chunks 0..2
            #pragma unroll
            for (int c0 = 0; c0 < 3; c0++) {
                const char* src = (const char*)hT + (size_t)c0 * CBYTES;
                char* dst = (char*)Asmem + (size_t)(c0 & 3) * CBYTES;
                #pragma unroll
                for (int i = 0; i < 8; i++) {
                    int off = (i * 256 + tid) * 16;
                    cpa16(dst + off, src + off);
                }
                CP_COMMIT();
            }

            for (int c = 0; c < NCHUNK; c++) {
                if (c + 3 < NCHUNK) {
                    const char* src = (const char*)hT + (size_t)(c + 3) * CBYTES;
                    char* dst = (char*)Asmem + (size_t)((c + 3) & 3) * CBYTES;
                    #pragma unroll
                    for (int i = 0; i < 8; i++) {
                        int off = (i * 256 + tid) * 16;
                        cpa16(dst + off, src + off);
                    }
                    CP_COMMIT();
                }
                if (c + 3 < NCHUNK)      CP_WAIT(3);
                else if (c == NCHUNK - 3) CP_WAIT(2);
                else if (c == NCHUNK - 2) CP_WAIT(1);
                else                      CP_WAIT(0);
                __syncthreads();

                const float* A = Asmem + (size_t)(c & 3) * (KC * 256) + b0;
                const unsigned long long* wp = ws2 + (size_t)c * KC * 16 + hg * 4;
                #pragma unroll 8
                for (int k = 0; k < KC; k++) {
                    ulonglong2 aq  = *(const ulonglong2*)(A + k * 256);
                    ulonglong2 w01 = *(const ulonglong2*)(wp + k * 16);
                    ulonglong2 w23 = *(const ulonglong2*)(wp + k * 16 + 2);
                    fma2(acc[0][0], aq.x, w01.x); fma2(acc[1][0], aq.y, w01.x);
                    fma2(acc[0][1], aq.x, w01.y); fma2(acc[1][1], aq.y, w01.y);
                    fma2(acc[0][2], aq.x, w23.x); fma2(acc[1][2], aq.y, w23.x);
                    fma2(acc[0][3], aq.x, w23.y); fma2(acc[1][3], aq.y, w23.y);
                }
                __syncthreads();
            }
        } else {
            CP_WAIT(0);
            __syncthreads();
        }

        float y[4][4];
        #pragma unroll
        for (int g = 0; g < 4; g++) {
            float2 lo = upk2(acc[0][g]);
            float2 hi = upk2(acc[1][g]);
            y[g][0] = lo.x; y[g][1] = lo.y; y[g][2] = hi.x; y[g][3] = hi.y;
        }

        float hn[4];
        #pragma unroll
        for (int r = 0; r < 4; r++) {
            int b = b0 + r;
            float xi = Gs[(0 * 256 + b) * 4 + hg] + y[0][r];
            float xf = Gs[(1 * 256 + b) * 4 + hg] + y[1][r];
            float xc = Gs[(2 * 256 + b) * 4 + hg] + y[2][r];
            float t1 = Gs[(3 * 256 + b) * 4 + hg];
            float t2 = Gs[(4 * 256 + b) * 4 + hg];
            float d1 = Gs[(5 * 256 + b) * 4 + hg];
            float d2 = Gs[(6 * 256 + b) * 4 + hg];
            float o  = Gs[(7 * 256 + b) * 4 + hg] + y[3][r];

            float it = sigf(xi);
            float ft = sigf(xf);
            float jj = tanh_fast(xc);
            float T1 = sigf(t1), T2 = sigf(t2), D1 = sigf(d1), D2 = sigf(d2);
            float fc = ft * cst[r];
            float ij = it * jj;
            float chat = fc + ij * T1 * D1;
            float cnew = fc + ij * T2 * D2;
            float ot = sigf(o);
            hn[r] = ot * tanh_fast(chat);
            cst[r] = cnew;
        }

        // next-step hidden state: [h][b], float4 over b
        *(float4*)&hTn[(h0 + hg) * BB + b0] = make_float4(hn[0], hn[1], hn[2], hn[3]);

        // stage hn (and c at last step) so each thread emits ONE STG.128
        float* hs = Asmem;              // buffers idle until after barrier
        float* cs = Asmem + 4096;
        #pragma unroll
        for (int r = 0; r < 4; r++) hs[(b0 + r) * 4 + hg] = hn[r];
        if (t == SS - 1) {
            #pragma unroll
            for (int r = 0; r < 4; r++) cs[(b0 + r) * 4 + hg] = cst[r];
        }
        __syncthreads();
        {
            float4 v = *(const float4*)&hs[tid * 4];
            *(float4*)&out[((size_t)tid * SS + t) * HH + h0] = v;
            if (t == SS - 1) {
                unsigned long long base = (unsigned long long)BB * SS * HH;
                unsigned long long o1 = base + (unsigned long long)tid * HH + h0;
                unsigned long long o2 = o1 + (unsigned long long)BB * HH;
                if (o1 + 4 <= out_size) *(float4*)&out[o1] = v;
                if (o2 + 4 <= out_size) *(float4*)&out[o2] = *(const float4*)&cs[tid * 4];
            }
        }

        if (t < SS - 1) {
            // grid barrier: single elected fence/atomic
            __syncthreads();
            if (tid == 0) {
                __threadfence();
                atomicAdd(&g_count, 1u);
                unsigned target = (unsigned)(t + 1) * (unsigned)NBLK;
                while (ld_cg_u32(&g_count) < target) { __nanosleep(20); }
                __threadfence();
            }
            __syncthreads();
        }
    }

    // Self-resetting counter for deterministic graph replays
    if (tid == 0) {
        unsigned old = atomicAdd(&g_count, 1u);
        if (old == (unsigned)(SS * NBLK - 1)) atomicExch(&g_count, 0u);
    }
}

extern "C" void kernel_launch(void* const* d_in, const int* in_sizes, int n_in,
                              void* d_out, int out_size) {
    const float* x = (const float*)d_in[0];

    ProjArgs pa = {};
    pa.x = x;
    pa.Wx[0] = (const float*)d_in[1];  pa.bias[0] = (const float*)d_in[3];
    pa.Wx[1] = (const float*)d_in[4];  pa.bias[1] = (const float*)d_in[6];
    pa.Wx[2] = (const float*)d_in[7];  pa.bias[2] = (const float*)d_in[9];
    pa.Wx[3] = (const float*)d_in[10]; pa.aux1[3] = (const float*)d_in[11]; pa.bias[3] = (const float*)d_in[12];
    pa.Wx[4] = (const float*)d_in[13]; pa.aux1[4] = (const float*)d_in[14]; pa.bias[4] = (const float*)d_in[15];
    pa.Wx[5] = (const float*)d_in[16]; pa.aux1[5] = (const float*)d_in[17]; pa.bias[5] = (const float*)d_in[18];
    pa.Wx[6] = (const float*)d_in[19]; pa.aux1[6] = (const float*)d_in[20]; pa.bias[6] = (const float*)d_in[21];
    pa.Wx[7] = (const float*)d_in[22]; pa.aux1[7] = (const float*)d_in[24]; pa.aux2[7] = (const float*)d_in[25];
    pa.bias[7] = (const float*)d_in[26];

    const float* Whi = (const float*)d_in[2];
    const float* Whf = (const float*)d_in[5];
    const float* Whc = (const float*)d_in[8];
    const float* Who = (const float*)d_in[23];

    float* out = (float*)d_out;

    cudaFuncSetAttribute(rec_kernel, cudaFuncAttributeMaxDynamicSharedMemorySize,
                         SM_TOTAL);

    dim3 pgrid(HH / 64, (BB * SS) / 64, 8);
    proj_kernel<<<pgrid, 256>>>(pa);

    rec_kernel<<<NBLK, 256, SM_TOTAL>>>(Whi, Whf, Whc, Who, out,
                                        (unsigned long long)out_size);
}